// round 1
// baseline (speedup 1.0000x reference)
#include <cuda_runtime.h>
#include <math.h>

typedef unsigned long long ull;

#define N_B 8
#define C_IN 64
#define C_H 32
#define HI 384
#define WI 384
#define HO 192
#define WO 192
#define HWI (HI*WI)
#define HWO (HO*WO)
#define NPIX_CH (N_B*HWO)   // 294912 elements per channel for BN stats

// ---------------- scratch (device globals; no runtime allocation) ----------------
__device__ float g_mean[N_B*C_IN];
__device__ float g_att[2*N_B*4];
__device__ float g_sqw[C_IN*9*128];          // [ci][k9][co*2 duplicated]
__device__ float g_wv[N_B*C_H*3*64];         // [n][ci][kh][co*2 duplicated]
__device__ float g_wh[N_B*C_H*3*64];         // [n][ci][kw][co*2 duplicated]
__device__ float g_vraw[(size_t)N_B*C_H*HWO];
__device__ float g_hraw[(size_t)N_B*C_H*HWO];
__device__ float g_stats[2*C_H*2];           // [(dir*32+c)*2 + {sum, sumsq}]

// ---------------- f32x2 packed math helpers ----------------
__device__ __forceinline__ ull pack2(float a, float b) {
    ull r; asm("mov.b64 %0, {%1, %2};" : "=l"(r) : "f"(a), "f"(b)); return r;
}
__device__ __forceinline__ void unpack2(ull v, float& a, float& b) {
    asm("mov.b64 {%0, %1}, %2;" : "=f"(a), "=f"(b) : "l"(v));
}
__device__ __forceinline__ void ffma2(ull& d, ull a, ull b) {
    asm("fma.rn.f32x2 %0, %1, %2, %0;" : "+l"(d) : "l"(a), "l"(b));
}

// ---------------- 1) per-(n,c) channel means of x ----------------
__global__ void mean_kernel(const float* __restrict__ x) {
    int nc = blockIdx.x;                       // n*64 + c, 512 blocks
    const float4* p = (const float4*)(x + (size_t)nc * HWI);
    float s = 0.f;
    for (int i = threadIdx.x; i < HWI/4; i += 256) {
        float4 v = p[i];
        s += v.x + v.y + v.z + v.w;
    }
    __shared__ float red[256];
    red[threadIdx.x] = s; __syncthreads();
    for (int o = 128; o > 0; o >>= 1) {
        if (threadIdx.x < o) red[threadIdx.x] += red[threadIdx.x + o];
        __syncthreads();
    }
    if (threadIdx.x == 0) g_mean[nc] = red[0] * (1.f / (float)HWI);
}

// ---------------- 2) attention sigmoid + zero stats ----------------
__global__ void att_kernel(const float* __restrict__ aw_v, const float* __restrict__ ab_v,
                           const float* __restrict__ aw_h, const float* __restrict__ ab_h) {
    int t = threadIdx.x;   // 128 threads
    if (t < 64) {
        int dir = t >> 5, n = (t >> 2) & 7, k = t & 3;
        const float* aw = dir ? aw_h : aw_v;
        const float* ab = dir ? ab_h : ab_v;
        const float* m = g_mean + n * C_IN + dir * C_H;
        float s = ab[k];
        #pragma unroll
        for (int ci = 0; ci < C_H; ci++) s += m[ci] * aw[k * C_H + ci];
        g_att[t] = 1.f / (1.f + expf(-s));
    }
    if (t < 128) g_stats[t] = 0.f;
}

// ---------------- 3) weight transpose + expert aggregation (duplicated pairs) ----------------
__global__ void prep_kernel(const float* __restrict__ sq_w,
                            const float* __restrict__ w_v, const float* __restrict__ w_h) {
    int idx = blockIdx.x * 256 + threadIdx.x;
    if (idx < C_IN*9*64) {
        int co = idx & 63, k = (idx >> 6) % 9, ci = idx / 576;
        float w = sq_w[(co * C_IN + ci) * 9 + k];
        int o = (ci * 9 + k) * 128 + co * 2;
        g_sqw[o] = w; g_sqw[o + 1] = w;
    } else if (idx < C_IN*9*64 + 2*24576) {
        int r = idx - C_IN*9*64;
        int dir = r / 24576; r %= 24576;
        int co = r & 31, kh = (r >> 5) % 3, ci = (r / 96) & 31, n = r / 3072;
        const float* w = dir ? w_h : w_v;
        const float* att = &g_att[dir * 32 + n * 4];
        float v = 0.f;
        #pragma unroll
        for (int k = 0; k < 4; k++) v += att[k] * w[((k * 32 + co) * 32 + ci) * 3 + kh];
        float* dst = dir ? g_wh : g_wv;
        int o = ((n * 32 + ci) * 3 + kh) * 64 + co * 2;
        dst[o] = v; dst[o + 1] = v;
    }
}

// ---------------- 4) square 3x3 s2 conv, fused bias + channel shuffle ----------------
// Tile: 32 out-x * 4 out-y * 64 co per block; thread = 2x (packed) * 2y * 8co.
__global__ void __launch_bounds__(256, 2)
sq_kernel(const float* __restrict__ x, const float* __restrict__ sq_b, float* __restrict__ out) {
    __shared__ __align__(16) float s_in[4*9*68];   // ci chunk 4, 9 rows, 65(+pad) cols
    __shared__ __align__(16) float s_w[4*9*128];   // [ci][k][co*2]
    const int tid = threadIdx.x;
    const int tx = tid & 15, ty = (tid >> 4) & 1, tc = tid >> 5;   // warp == tc
    const int x0 = blockIdx.x * 32, y0 = blockIdx.y * 4, n = blockIdx.z;
    const int gx0 = 2*x0 - 1, gy0 = 2*y0 - 1;

    ull acc[2][8];
    #pragma unroll
    for (int a = 0; a < 2; a++)
        #pragma unroll
        for (int b = 0; b < 8; b++) acc[a][b] = 0ULL;

    for (int ci0 = 0; ci0 < C_IN; ci0 += 4) {
        __syncthreads();
        // input tile: 4 ci * 9 rows * 65 cols
        for (int i = tid; i < 4*9*65; i += 256) {
            int c = i % 65, r = (i / 65) % 9, ci = i / 585;
            int gy = gy0 + r, gx = gx0 + c;
            float v = 0.f;
            if (gy >= 0 && gx >= 0)
                v = x[((size_t)(n * C_IN + ci0 + ci) * HI + gy) * WI + gx];
            s_in[(ci * 9 + r) * 68 + c] = v;
        }
        // weights: 4*9*128 floats = 1152 float4 (already transposed+duplicated)
        {
            const float4* src = (const float4*)(g_sqw + ci0 * 9 * 128);
            float4* dst = (float4*)s_w;
            for (int i = tid; i < 1152; i += 256) dst[i] = src[i];
        }
        __syncthreads();

        #pragma unroll
        for (int ci = 0; ci < 4; ci++) {
            #pragma unroll
            for (int kh = 0; kh < 3; kh++) {
                const int r0 = 4 * ty + kh;
                const float* row0 = &s_in[(ci * 9 + r0) * 68 + 4 * tx];
                const float* row1 = row0 + 2 * 68;
                float4 a0 = *(const float4*)row0; float e0 = row0[4];
                float4 a1 = *(const float4*)row1; float e1 = row1[4];
                ull p0[3] = { pack2(a0.x, a0.z), pack2(a0.y, a0.w), pack2(a0.z, e0) };
                ull p1[3] = { pack2(a1.x, a1.z), pack2(a1.y, a1.w), pack2(a1.z, e1) };
                #pragma unroll
                for (int kw = 0; kw < 3; kw++) {
                    const float* wp = &s_w[(ci * 9 + kh * 3 + kw) * 128 + tc * 16];
                    ulonglong2 wA = *(const ulonglong2*)(wp);
                    ulonglong2 wB = *(const ulonglong2*)(wp + 4);
                    ulonglong2 wC = *(const ulonglong2*)(wp + 8);
                    ulonglong2 wD = *(const ulonglong2*)(wp + 12);
                    ffma2(acc[0][0], p0[kw], wA.x); ffma2(acc[0][1], p0[kw], wA.y);
                    ffma2(acc[0][2], p0[kw], wB.x); ffma2(acc[0][3], p0[kw], wB.y);
                    ffma2(acc[0][4], p0[kw], wC.x); ffma2(acc[0][5], p0[kw], wC.y);
                    ffma2(acc[0][6], p0[kw], wD.x); ffma2(acc[0][7], p0[kw], wD.y);
                    ffma2(acc[1][0], p1[kw], wA.x); ffma2(acc[1][1], p1[kw], wA.y);
                    ffma2(acc[1][2], p1[kw], wB.x); ffma2(acc[1][3], p1[kw], wB.y);
                    ffma2(acc[1][4], p1[kw], wC.x); ffma2(acc[1][5], p1[kw], wC.y);
                    ffma2(acc[1][6], p1[kw], wD.x); ffma2(acc[1][7], p1[kw], wD.y);
                }
            }
        }
    }
    // epilogue: bias + channel shuffle (concat ch c -> out ch (c%16)*8 + c/16)
    #pragma unroll
    for (int j = 0; j < 8; j++) {
        int co = tc * 8 + j;
        float bias = sq_b[co];
        int oc = ((co & 15) << 3) + (co >> 4);
        #pragma unroll
        for (int yy = 0; yy < 2; yy++) {
            int y = y0 + 2 * ty + yy;
            float lo, hi; unpack2(acc[yy][j], lo, hi);
            *(float2*)&out[((size_t)(n * 128 + oc) * HO + y) * WO + x0 + 2 * tx] =
                make_float2(lo + bias, hi + bias);
        }
    }
}

// ---------------- 5) vertical CondConv (3x1, s2, pad (1,0)) -> g_vraw ----------------
// Tile: 32 out-x * 4 out-y * 32 co; thread = 2x (packed) * 1y * 8co.
__global__ void __launch_bounds__(256)
v_kernel(const float* __restrict__ x) {
    __shared__ __align__(16) float s_in[16*9*32];  // even input cols only
    __shared__ __align__(16) float s_w[16*3*64];
    const int tid = threadIdx.x;
    const int tx = tid & 15, ty = (tid >> 4) & 3, tc = tid >> 6;
    const int x0 = blockIdx.x * 32, y0 = blockIdx.y * 4, n = blockIdx.z;
    const int gy0 = 2*y0 - 1;
    ull acc[8];
    #pragma unroll
    for (int j = 0; j < 8; j++) acc[j] = 0ULL;

    for (int ci0 = 0; ci0 < C_H; ci0 += 16) {
        __syncthreads();
        for (int i = tid; i < 16*9*32; i += 256) {
            int c = i & 31, r = (i >> 5) % 9, ci = i / 288;
            int gy = gy0 + r;
            float v = 0.f;
            if (gy >= 0)
                v = x[((size_t)(n * C_IN + ci0 + ci) * HI + gy) * WI + 2 * (x0 + c)];
            s_in[(ci * 9 + r) * 32 + c] = v;
        }
        {
            const float4* src = (const float4*)(g_wv + (size_t)(n * 32 + ci0) * 192);
            float4* dst = (float4*)s_w;
            for (int i = tid; i < 768; i += 256) dst[i] = src[i];
        }
        __syncthreads();
        #pragma unroll
        for (int ci = 0; ci < 16; ci++) {
            #pragma unroll
            for (int kh = 0; kh < 3; kh++) {
                int r = 2 * ty + kh;
                ull in2 = *(const ull*)&s_in[(ci * 9 + r) * 32 + 2 * tx];
                const float* wp = &s_w[(ci * 3 + kh) * 64 + tc * 16];
                ulonglong2 wA = *(const ulonglong2*)(wp);
                ulonglong2 wB = *(const ulonglong2*)(wp + 4);
                ulonglong2 wC = *(const ulonglong2*)(wp + 8);
                ulonglong2 wD = *(const ulonglong2*)(wp + 12);
                ffma2(acc[0], in2, wA.x); ffma2(acc[1], in2, wA.y);
                ffma2(acc[2], in2, wB.x); ffma2(acc[3], in2, wB.y);
                ffma2(acc[4], in2, wC.x); ffma2(acc[5], in2, wC.y);
                ffma2(acc[6], in2, wD.x); ffma2(acc[7], in2, wD.y);
            }
        }
    }
    int y = y0 + ty;
    #pragma unroll
    for (int j = 0; j < 8; j++) {
        int co = tc * 8 + j;
        float lo, hi; unpack2(acc[j], lo, hi);
        *(float2*)&g_vraw[((size_t)(n * 32 + co) * HO + y) * WO + x0 + 2 * tx] =
            make_float2(lo, hi);
    }
}

// ---------------- 6) horizontal CondConv (1x3, s2, pad (0,1)) -> g_hraw ----------------
__global__ void __launch_bounds__(256)
h_kernel(const float* __restrict__ x) {
    __shared__ __align__(16) float s_in[16*4*68];  // even input rows, full-width cols
    __shared__ __align__(16) float s_w[16*3*64];
    const int tid = threadIdx.x;
    const int tx = tid & 15, ty = (tid >> 4) & 3, tc = tid >> 6;
    const int x0 = blockIdx.x * 32, y0 = blockIdx.y * 4, n = blockIdx.z;
    const int gx0 = 2*x0 - 1;
    ull acc[8];
    #pragma unroll
    for (int j = 0; j < 8; j++) acc[j] = 0ULL;

    for (int ci0 = 0; ci0 < C_H; ci0 += 16) {
        __syncthreads();
        for (int i = tid; i < 16*4*65; i += 256) {
            int c = i % 65, r = (i / 65) & 3, ci = i / 260;
            int gx = gx0 + c, gy = 2 * (y0 + r);
            float v = 0.f;
            if (gx >= 0)
                v = x[((size_t)(n * C_IN + C_H + ci0 + ci) * HI + gy) * WI + gx];
            s_in[(ci * 4 + r) * 68 + c] = v;
        }
        {
            const float4* src = (const float4*)(g_wh + (size_t)(n * 32 + ci0) * 192);
            float4* dst = (float4*)s_w;
            for (int i = tid; i < 768; i += 256) dst[i] = src[i];
        }
        __syncthreads();
        #pragma unroll
        for (int ci = 0; ci < 16; ci++) {
            const float* row = &s_in[(ci * 4 + ty) * 68 + 4 * tx];
            float4 a = *(const float4*)row; float e = row[4];
            ull p[3] = { pack2(a.x, a.z), pack2(a.y, a.w), pack2(a.z, e) };
            #pragma unroll
            for (int kw = 0; kw < 3; kw++) {
                const float* wp = &s_w[(ci * 3 + kw) * 64 + tc * 16];
                ulonglong2 wA = *(const ulonglong2*)(wp);
                ulonglong2 wB = *(const ulonglong2*)(wp + 4);
                ulonglong2 wC = *(const ulonglong2*)(wp + 8);
                ulonglong2 wD = *(const ulonglong2*)(wp + 12);
                ffma2(acc[0], p[kw], wA.x); ffma2(acc[1], p[kw], wA.y);
                ffma2(acc[2], p[kw], wB.x); ffma2(acc[3], p[kw], wB.y);
                ffma2(acc[4], p[kw], wC.x); ffma2(acc[5], p[kw], wC.y);
                ffma2(acc[6], p[kw], wD.x); ffma2(acc[7], p[kw], wD.y);
            }
        }
    }
    int y = y0 + ty;
    #pragma unroll
    for (int j = 0; j < 8; j++) {
        int co = tc * 8 + j;
        float lo, hi; unpack2(acc[j], lo, hi);
        *(float2*)&g_hraw[((size_t)(n * 32 + co) * HO + y) * WO + x0 + 2 * tx] =
            make_float2(lo, hi);
    }
}

// ---------------- 7) BN statistics (sum / sumsq per channel) ----------------
__global__ void stats_kernel() {
    int bid = blockIdx.x;                       // 256 blocks
    int dir = bid >> 7, c = (bid >> 2) & 31, sl = bid & 3;
    const float* base = dir ? g_hraw : g_vraw;
    float s = 0.f, q = 0.f;
    for (int i = threadIdx.x; i < 18432; i += 256) {
        int e4 = sl * 18432 + i;                // float4 index over 294912 elems
        int n = e4 / 9216, ri = e4 % 9216;
        float4 v = ((const float4*)(base + (size_t)(n * 32 + c) * HWO))[ri];
        s += v.x + v.y + v.z + v.w;
        q += v.x * v.x + v.y * v.y + v.z * v.z + v.w * v.w;
    }
    __shared__ float red[512];
    red[threadIdx.x] = s; red[256 + threadIdx.x] = q;
    __syncthreads();
    for (int o = 128; o > 0; o >>= 1) {
        if (threadIdx.x < o) {
            red[threadIdx.x] += red[threadIdx.x + o];
            red[256 + threadIdx.x] += red[256 + threadIdx.x + o];
        }
        __syncthreads();
    }
    if (threadIdx.x == 0) {
        atomicAdd(&g_stats[(dir * 32 + c) * 2],     red[0]);
        atomicAdd(&g_stats[(dir * 32 + c) * 2 + 1], red[256]);
    }
}

// ---------------- 8) BN apply + channel shuffle write ----------------
__global__ void bn_kernel(const float* __restrict__ gv, const float* __restrict__ bv,
                          const float* __restrict__ gh, const float* __restrict__ bh,
                          float* __restrict__ out) {
    int bid = blockIdx.x;                       // 512 blocks
    int dir = bid >> 8, co = (bid >> 3) & 31, n = bid & 7;
    float sum = g_stats[(dir * 32 + co) * 2];
    float sq  = g_stats[(dir * 32 + co) * 2 + 1];
    const float inv = 1.f / (float)NPIX_CH;
    float m = sum * inv;
    float var = sq * inv - m * m;
    float gam = (dir ? gh : gv)[co];
    float bet = (dir ? bh : bv)[co];
    float scale = gam * rsqrtf(var + 1e-5f);
    float shift = bet - m * scale;
    int oc = ((co & 15) << 3) + 4 + 2 * dir + (co >> 4);
    const float4* src = (const float4*)((dir ? g_hraw : g_vraw) + (size_t)(n * 32 + co) * HWO);
    float4* dst = (float4*)(out + (size_t)(n * 128 + oc) * HWO);
    for (int i = threadIdx.x; i < 9216; i += 256) {
        float4 v = src[i];
        v.x = v.x * scale + shift; v.y = v.y * scale + shift;
        v.z = v.z * scale + shift; v.w = v.w * scale + shift;
        dst[i] = v;
    }
}

// ---------------- launch ----------------
extern "C" void kernel_launch(void* const* d_in, const int* in_sizes, int n_in,
                              void* d_out, int out_size) {
    const float* x      = (const float*)d_in[0];
    const float* sq_w   = (const float*)d_in[1];
    const float* sq_b   = (const float*)d_in[2];
    const float* aw_v   = (const float*)d_in[3];
    const float* ab_v   = (const float*)d_in[4];
    const float* w_v    = (const float*)d_in[5];
    const float* bn_v_g = (const float*)d_in[6];
    const float* bn_v_b = (const float*)d_in[7];
    const float* aw_h   = (const float*)d_in[8];
    const float* ab_h   = (const float*)d_in[9];
    const float* w_h    = (const float*)d_in[10];
    const float* bn_h_g = (const float*)d_in[11];
    const float* bn_h_b = (const float*)d_in[12];
    float* out = (float*)d_out;

    mean_kernel<<<N_B * C_IN, 256>>>(x);
    att_kernel<<<1, 128>>>(aw_v, ab_v, aw_h, ab_h);
    prep_kernel<<<336, 256>>>(sq_w, w_v, w_h);
    sq_kernel<<<dim3(WO/32, HO/4, N_B), 256>>>(x, sq_b, out);
    v_kernel<<<dim3(WO/32, HO/4, N_B), 256>>>(x);
    h_kernel<<<dim3(WO/32, HO/4, N_B), 256>>>(x);
    stats_kernel<<<256, 256>>>();
    bn_kernel<<<512, 256>>>(bn_v_g, bn_v_b, bn_h_g, bn_h_b, out);
}